// round 1
// baseline (speedup 1.0000x reference)
#include <cuda_runtime.h>
#include <cuda_bf16.h>
#include <math.h>

#define SEQ 2048
#define HDIM 1024
#define NLAYER 4
#define NH 16
#define NKV 4
#define HD 64
#define IDIM 4096
#define VOCAB 32000

// ---------------- scratch (static device globals; no allocations) ----------------
__device__ float g_h[SEQ * HDIM];
__device__ float g_norm[SEQ * HDIM];
__device__ float g_q[SEQ * NH * HD];
__device__ float g_kraw[SEQ * NKV * HD];
__device__ float g_kT[NKV * HD * SEQ];   // [kvh][d][s]
__device__ float g_v[SEQ * NKV * HD];
__device__ float g_att[SEQ * NH * HD];
__device__ float g_gate[SEQ * IDIM];
__device__ float g_up[SEQ * IDIM];

// ---------------- embedding + audio scatter ----------------
__global__ void embed_scatter_kernel(const int* __restrict__ ids,
                                     const float* __restrict__ emb,
                                     const float* __restrict__ audio,
                                     const int* __restrict__ aoff,
                                     float* __restrict__ h) {
    int s = blockIdx.x;
    int off = aoff[0];
    const float* src;
    if (s >= off && s < off + 256) src = audio + (size_t)(s - off) * HDIM;
    else                           src = emb + (size_t)ids[s] * HDIM;
    float* dst = h + (size_t)s * HDIM;
    int i = threadIdx.x * 4;
    *(float4*)&dst[i] = *(const float4*)&src[i];
}

// ---------------- RMSNorm over H=1024 ----------------
__global__ void rmsnorm_kernel(const float* __restrict__ x,
                               const float* __restrict__ w,
                               float* __restrict__ out) {
    int s = blockIdx.x;
    const float* xr = x + (size_t)s * HDIM;
    float ss = 0.f;
#pragma unroll
    for (int i = 0; i < 4; i++) { float v = xr[threadIdx.x + i * 256]; ss += v * v; }
    __shared__ float red[8];
#pragma unroll
    for (int o = 16; o; o >>= 1) ss += __shfl_xor_sync(0xffffffffu, ss, o);
    if ((threadIdx.x & 31) == 0) red[threadIdx.x >> 5] = ss;
    __syncthreads();
    if (threadIdx.x < 32) {
        float v = (threadIdx.x < 8) ? red[threadIdx.x] : 0.f;
#pragma unroll
        for (int o = 4; o; o >>= 1) v += __shfl_xor_sync(0xffffffffu, v, o);
        if (threadIdx.x == 0) red[0] = v;
    }
    __syncthreads();
    float r = rsqrtf(red[0] * (1.f / HDIM) + 1e-6f);
    float* orow = out + (size_t)s * HDIM;
#pragma unroll
    for (int i = 0; i < 4; i++) { int id = threadIdx.x + i * 256; orow[id] = xr[id] * r * w[id]; }
}

// ---------------- per-head RMSNorm (HD=64) + RoPE ----------------
// one warp per (s, head). lane handles dims (lane, lane+32) which pair under rotate_half.
__global__ void rms_rope_kernel(const float* __restrict__ in,
                                const float* __restrict__ w,
                                const int* __restrict__ pos_ids,
                                float* __restrict__ out_nat,
                                float* __restrict__ out_T,
                                float* __restrict__ present,
                                int nh) {
    int s = blockIdx.x;
    int warp = threadIdx.x >> 5, lane = threadIdx.x & 31;
    int h = blockIdx.y * 4 + warp;
    if (h >= nh) return;
    const float* x = in + (size_t)s * nh * HD + h * HD;
    float x0 = x[lane], x1 = x[lane + 32];
    float ss = x0 * x0 + x1 * x1;
#pragma unroll
    for (int o = 16; o; o >>= 1) ss += __shfl_xor_sync(0xffffffffu, ss, o);
    float r = rsqrtf(ss * (1.f / HD) + 1e-6f);
    x0 = x0 * r * w[lane];
    x1 = x1 * r * w[lane + 32];
    float pos = (float)pos_ids[s];
    // inv_freq[j] = 10000^{-j/32}
    float invf = expf(-((float)lane * (1.f / 32.f)) * 9.210340371976184f);
    float ang = pos * invf;
    float c, sn;
    sincosf(ang, &sn, &c);
    float o0 = x0 * c - x1 * sn;
    float o1 = x1 * c + x0 * sn;
    if (out_nat) {
        float* op = out_nat + (size_t)s * nh * HD + h * HD;
        op[lane] = o0; op[lane + 32] = o1;
    }
    if (out_T) {
        out_T[(size_t)(h * HD + lane) * SEQ + s] = o0;
        out_T[(size_t)(h * HD + lane + 32) * SEQ + s] = o1;
    }
    if (present) {
        float* pp = present + ((size_t)h * SEQ + s) * HD;
        pp[lane] = o0; pp[lane + 32] = o1;
    }
}

// ---------------- copy V into present_values [NKV,S,HD] ----------------
__global__ void copy_v_kernel(const float* __restrict__ v, float* __restrict__ pv) {
    int s = blockIdx.x;
    int t = threadIdx.x;           // 256 = NKV*HD
    int kv = t >> 6, d = t & 63;
    pv[((size_t)kv * SEQ + s) * HD + d] = v[(size_t)s * (NKV * HD) + t];
}

// ---------------- GEMM: C[M,N] = (Res?) + A[M,K] @ B[K,N]  (128x128x16 tiles) ----------------
__global__ __launch_bounds__(256) void gemm_kernel(const float* __restrict__ A,
                                                   const float* __restrict__ B,
                                                   const float* __restrict__ Res,
                                                   float* __restrict__ C,
                                                   int M, int N, int K) {
    __shared__ float As[16][128];   // [k][m]
    __shared__ float Bs[16][128];   // [k][n]
    int bm = blockIdx.y * 128, bn = blockIdx.x * 128;
    int tid = threadIdx.x;
    int tm = (tid >> 4) << 3;   // 0..120
    int tn = (tid & 15) << 3;
    float acc[8][8];
#pragma unroll
    for (int i = 0; i < 8; i++)
#pragma unroll
        for (int j = 0; j < 8; j++) acc[i][j] = 0.f;

    for (int k0 = 0; k0 < K; k0 += 16) {
#pragma unroll
        for (int it = 0; it < 2; it++) {
            int idx = tid + it * 256;              // 0..511 float4s
            int m = idx >> 2, kv4 = (idx & 3) << 2;
            float4 a4 = *(const float4*)(A + (size_t)(bm + m) * K + k0 + kv4);
            As[kv4 + 0][m] = a4.x; As[kv4 + 1][m] = a4.y;
            As[kv4 + 2][m] = a4.z; As[kv4 + 3][m] = a4.w;
        }
#pragma unroll
        for (int it = 0; it < 2; it++) {
            int idx = tid + it * 256;
            int kk = idx >> 5, nv = (idx & 31) << 2;
            *(float4*)&Bs[kk][nv] = *(const float4*)(B + (size_t)(k0 + kk) * N + bn + nv);
        }
        __syncthreads();
#pragma unroll
        for (int kk = 0; kk < 16; kk++) {
            float a[8], b[8];
            *(float4*)&a[0] = *(float4*)&As[kk][tm];
            *(float4*)&a[4] = *(float4*)&As[kk][tm + 4];
            *(float4*)&b[0] = *(float4*)&Bs[kk][tn];
            *(float4*)&b[4] = *(float4*)&Bs[kk][tn + 4];
#pragma unroll
            for (int i = 0; i < 8; i++)
#pragma unroll
                for (int j = 0; j < 8; j++) acc[i][j] += a[i] * b[j];
        }
        __syncthreads();
    }
#pragma unroll
    for (int i = 0; i < 8; i++) {
        size_t row = (size_t)(bm + tm + i);
#pragma unroll
        for (int j = 0; j < 8; j += 4) {
            float4 o;
            if (Res) {
                float4 rr = *(const float4*)(Res + row * N + bn + tn + j);
                o.x = rr.x + acc[i][j + 0]; o.y = rr.y + acc[i][j + 1];
                o.z = rr.z + acc[i][j + 2]; o.w = rr.w + acc[i][j + 3];
            } else {
                o.x = acc[i][j + 0]; o.y = acc[i][j + 1];
                o.z = acc[i][j + 2]; o.w = acc[i][j + 3];
            }
            *(float4*)(C + row * N + bn + tn + j) = o;
        }
    }
}

// ---------------- flash attention: 64q x 64k tiles, online softmax ----------------
// grid (32 qtiles, 16 heads), 256 threads (16x16, 4x4 per thread)
__global__ __launch_bounds__(256) void attn_kernel(const float* __restrict__ q,
                                                   const float* __restrict__ kT,
                                                   const float* __restrict__ v,
                                                   float* __restrict__ o) {
    extern __shared__ float sm[];
    float* Qs  = sm;           // [64][64] row-major [r][d]
    float* Kst = sm + 4096;    // [d][j]
    float* Vs  = sm + 8192;    // [j][d]
    float* Ps  = sm + 12288;   // [r][j]
    int qt = blockIdx.x, h = blockIdx.y, kvh = h >> 2;
    int tid = threadIdx.x;
    int tr = tid >> 4, tc = tid & 15;

#pragma unroll
    for (int it = 0; it < 4; it++) {
        int idx = tid + it * 256;
        int rr = idx >> 4, dv = (idx & 15) << 2;
        *(float4*)&Qs[rr * 64 + dv] =
            *(const float4*)&q[(size_t)(qt * 64 + rr) * (NH * HD) + h * HD + dv];
    }

    float m[4], l[4], acc[4][4];
#pragma unroll
    for (int i = 0; i < 4; i++) {
        m[i] = -1e30f; l[i] = 0.f;
#pragma unroll
        for (int j = 0; j < 4; j++) acc[i][j] = 0.f;
    }

    for (int kt = 0; kt <= qt; kt++) {
        __syncthreads();   // also covers initial Qs load visibility
#pragma unroll
        for (int it = 0; it < 4; it++) {
            int idx = tid + it * 256;
            int a = idx >> 4, bv = (idx & 15) << 2;
            *(float4*)&Kst[a * 64 + bv] =
                *(const float4*)&kT[(size_t)(kvh * HD + a) * SEQ + kt * 64 + bv];
            *(float4*)&Vs[a * 64 + bv] =
                *(const float4*)&v[(size_t)(kt * 64 + a) * (NKV * HD) + kvh * HD + bv];
        }
        __syncthreads();

        float sc[4][4];
#pragma unroll
        for (int i = 0; i < 4; i++)
#pragma unroll
            for (int j = 0; j < 4; j++) sc[i][j] = 0.f;

#pragma unroll 8
        for (int d = 0; d < 64; d++) {
            float4 b = *(float4*)&Kst[d * 64 + tc * 4];
            float a0 = Qs[(tr * 4 + 0) * 64 + d];
            float a1 = Qs[(tr * 4 + 1) * 64 + d];
            float a2 = Qs[(tr * 4 + 2) * 64 + d];
            float a3 = Qs[(tr * 4 + 3) * 64 + d];
            sc[0][0] += a0 * b.x; sc[0][1] += a0 * b.y; sc[0][2] += a0 * b.z; sc[0][3] += a0 * b.w;
            sc[1][0] += a1 * b.x; sc[1][1] += a1 * b.y; sc[1][2] += a1 * b.z; sc[1][3] += a1 * b.w;
            sc[2][0] += a2 * b.x; sc[2][1] += a2 * b.y; sc[2][2] += a2 * b.z; sc[2][3] += a2 * b.w;
            sc[3][0] += a3 * b.x; sc[3][1] += a3 * b.y; sc[3][2] += a3 * b.z; sc[3][3] += a3 * b.w;
        }

        bool diag = (kt == qt);
#pragma unroll
        for (int i = 0; i < 4; i++) {
            int qrow = qt * 64 + tr * 4 + i;
            float tm_ = -1e30f;
#pragma unroll
            for (int j = 0; j < 4; j++) {
                float val = sc[i][j] * 0.125f;
                if (diag && (kt * 64 + tc * 4 + j) > qrow) val = -1e30f;
                sc[i][j] = val;
                tm_ = fmaxf(tm_, val);
            }
            tm_ = fmaxf(tm_, __shfl_xor_sync(0xffffffffu, tm_, 1));
            tm_ = fmaxf(tm_, __shfl_xor_sync(0xffffffffu, tm_, 2));
            tm_ = fmaxf(tm_, __shfl_xor_sync(0xffffffffu, tm_, 4));
            tm_ = fmaxf(tm_, __shfl_xor_sync(0xffffffffu, tm_, 8));
            float mn = fmaxf(m[i], tm_);
            float scal = expf(m[i] - mn);
            float ps = 0.f;
#pragma unroll
            for (int j = 0; j < 4; j++) {
                float p = expf(sc[i][j] - mn);
                sc[i][j] = p;
                ps += p;
            }
            ps += __shfl_xor_sync(0xffffffffu, ps, 1);
            ps += __shfl_xor_sync(0xffffffffu, ps, 2);
            ps += __shfl_xor_sync(0xffffffffu, ps, 4);
            ps += __shfl_xor_sync(0xffffffffu, ps, 8);
            l[i] = l[i] * scal + ps;
            m[i] = mn;
#pragma unroll
            for (int j = 0; j < 4; j++) {
                acc[i][j] *= scal;
                Ps[(tr * 4 + i) * 64 + tc * 4 + j] = sc[i][j];
            }
        }
        __syncwarp();

#pragma unroll 8
        for (int j = 0; j < 64; j++) {
            float4 b = *(float4*)&Vs[j * 64 + tc * 4];
            float p0 = Ps[(tr * 4 + 0) * 64 + j];
            float p1 = Ps[(tr * 4 + 1) * 64 + j];
            float p2 = Ps[(tr * 4 + 2) * 64 + j];
            float p3 = Ps[(tr * 4 + 3) * 64 + j];
            acc[0][0] += p0 * b.x; acc[0][1] += p0 * b.y; acc[0][2] += p0 * b.z; acc[0][3] += p0 * b.w;
            acc[1][0] += p1 * b.x; acc[1][1] += p1 * b.y; acc[1][2] += p1 * b.z; acc[1][3] += p1 * b.w;
            acc[2][0] += p2 * b.x; acc[2][1] += p2 * b.y; acc[2][2] += p2 * b.z; acc[2][3] += p2 * b.w;
            acc[3][0] += p3 * b.x; acc[3][1] += p3 * b.y; acc[3][2] += p3 * b.z; acc[3][3] += p3 * b.w;
        }
    }

#pragma unroll
    for (int i = 0; i < 4; i++) {
        float inv = 1.f / l[i];
        int row = qt * 64 + tr * 4 + i;
        float4 ov;
        ov.x = acc[i][0] * inv; ov.y = acc[i][1] * inv;
        ov.z = acc[i][2] * inv; ov.w = acc[i][3] * inv;
        *(float4*)&o[(size_t)row * (NH * HD) + h * HD + tc * 4] = ov;
    }
}

// ---------------- silu(g) * u ----------------
__global__ void silu_mul_kernel(const float* __restrict__ g, const float* __restrict__ u,
                                float* __restrict__ out, int n) {
    int i = blockIdx.x * 256 + threadIdx.x;
    if (i < n) {
        float x = g[i];
        float sg = 1.f / (1.f + expf(-x));
        out[i] = x * sg * u[i];
    }
}

// ---------------- host launch ----------------
extern "C" void kernel_launch(void* const* d_in, const int* in_sizes, int n_in,
                              void* d_out, int out_size) {
    (void)in_sizes; (void)n_in; (void)out_size;

    static bool init = false;
    static float *p_h, *p_norm, *p_q, *p_kraw, *p_kT, *p_v, *p_att, *p_gate, *p_up;
    if (!init) {
        cudaGetSymbolAddress((void**)&p_h, g_h);
        cudaGetSymbolAddress((void**)&p_norm, g_norm);
        cudaGetSymbolAddress((void**)&p_q, g_q);
        cudaGetSymbolAddress((void**)&p_kraw, g_kraw);
        cudaGetSymbolAddress((void**)&p_kT, g_kT);
        cudaGetSymbolAddress((void**)&p_v, g_v);
        cudaGetSymbolAddress((void**)&p_att, g_att);
        cudaGetSymbolAddress((void**)&p_gate, g_gate);
        cudaGetSymbolAddress((void**)&p_up, g_up);
        cudaFuncSetAttribute(attn_kernel, cudaFuncAttributeMaxDynamicSharedMemorySize, 65536);
        init = true;
    }

    const int*   ids    = (const int*)d_in[0];
    const int*   pos    = (const int*)d_in[1];
    const float* audio  = (const float*)d_in[2];
    const int*   aoff   = (const int*)d_in[3];
    const float* embw   = (const float*)d_in[4];
    const float* q_w    = (const float*)d_in[5];
    const float* k_w    = (const float*)d_in[6];
    const float* v_w    = (const float*)d_in[7];
    const float* o_w    = (const float*)d_in[8];
    const float* qn_w   = (const float*)d_in[9];
    const float* kn_w   = (const float*)d_in[10];
    const float* ln1_w  = (const float*)d_in[11];
    const float* ln2_w  = (const float*)d_in[12];
    const float* gate_w = (const float*)d_in[13];
    const float* up_w   = (const float*)d_in[14];
    const float* down_w = (const float*)d_in[15];
    const float* norm_w = (const float*)d_in[16];
    const float* lm_w   = (const float*)d_in[17];

    float* out    = (float*)d_out;
    float* logits = out;
    float* pk     = out + (size_t)SEQ * VOCAB;
    float* pv     = pk + (size_t)NLAYER * NKV * SEQ * HD;

    embed_scatter_kernel<<<SEQ, 256>>>(ids, embw, audio, aoff, p_h);

    for (int l = 0; l < NLAYER; l++) {
        rmsnorm_kernel<<<SEQ, 256>>>(p_h, ln1_w + (size_t)l * HDIM, p_norm);

        gemm_kernel<<<dim3(NH * HD / 128, SEQ / 128), 256>>>(
            p_norm, q_w + (size_t)l * HDIM * NH * HD, nullptr, p_q, SEQ, NH * HD, HDIM);
        gemm_kernel<<<dim3(NKV * HD / 128, SEQ / 128), 256>>>(
            p_norm, k_w + (size_t)l * HDIM * NKV * HD, nullptr, p_kraw, SEQ, NKV * HD, HDIM);
        gemm_kernel<<<dim3(NKV * HD / 128, SEQ / 128), 256>>>(
            p_norm, v_w + (size_t)l * HDIM * NKV * HD, nullptr, p_v, SEQ, NKV * HD, HDIM);

        rms_rope_kernel<<<dim3(SEQ, 4), 128>>>(p_q, qn_w + (size_t)l * HD, pos,
                                               p_q, nullptr, nullptr, NH);
        rms_rope_kernel<<<dim3(SEQ, 1), 128>>>(p_kraw, kn_w + (size_t)l * HD, pos,
                                               nullptr, p_kT,
                                               pk + (size_t)l * NKV * SEQ * HD, NKV);
        copy_v_kernel<<<SEQ, 256>>>(p_v, pv + (size_t)l * NKV * SEQ * HD);

        attn_kernel<<<dim3(SEQ / 64, NH), 256, 65536>>>(p_q, p_kT, p_v, p_att);

        gemm_kernel<<<dim3(HDIM / 128, SEQ / 128), 256>>>(
            p_att, o_w + (size_t)l * NH * HD * HDIM, p_h, p_h, SEQ, HDIM, NH * HD);

        rmsnorm_kernel<<<SEQ, 256>>>(p_h, ln2_w + (size_t)l * HDIM, p_norm);

        gemm_kernel<<<dim3(IDIM / 128, SEQ / 128), 256>>>(
            p_norm, gate_w + (size_t)l * HDIM * IDIM, nullptr, p_gate, SEQ, IDIM, HDIM);
        gemm_kernel<<<dim3(IDIM / 128, SEQ / 128), 256>>>(
            p_norm, up_w + (size_t)l * HDIM * IDIM, nullptr, p_up, SEQ, IDIM, HDIM);

        silu_mul_kernel<<<(SEQ * IDIM) / 256, 256>>>(p_gate, p_up, p_gate, SEQ * IDIM);

        gemm_kernel<<<dim3(HDIM / 128, SEQ / 128), 256>>>(
            p_gate, down_w + (size_t)l * IDIM * HDIM, p_h, p_h, SEQ, HDIM, IDIM);
    }

    rmsnorm_kernel<<<SEQ, 256>>>(p_h, norm_w, p_norm);
    gemm_kernel<<<dim3(VOCAB / 128, SEQ / 128), 256>>>(
        p_norm, lm_w, nullptr, logits, SEQ, VOCAB, HDIM);
}